// round 11
// baseline (speedup 1.0000x reference)
#include <cuda_runtime.h>
#include <cstdint>

#define N_NODES 40000
#define N_EDGES 640000
#define IN_CH   128
#define OUT_CH  128
#define NUM_RBF 64
#define TILE16  16
#define NT16    (N_EDGES / TILE16)     // 40000 warp-tiles

// ---------------- device scratch (no allocs allowed) ----------------
__device__ float g_h[(size_t)N_NODES * OUT_CH];      // x @ Wl + bl

// ---------------- helpers ----------------
__device__ __forceinline__ float rnd_tf32(float x) {
    float r;
    asm("cvt.rna.tf32.f32 %0, %1;" : "=f"(r) : "f"(x));
    return r;
}
__device__ __forceinline__ uint32_t tf32_bits(float x) {
    return __float_as_uint(rnd_tf32(x));
}
__device__ __forceinline__ uint32_t smem_u32(const void* p) {
    uint32_t a;
    asm("{ .reg .u64 t; cvta.to.shared.u64 t, %1; cvt.u32.u64 %0, t; }"
        : "=r"(a) : "l"(p));
    return a;
}
__device__ __forceinline__ void red_add_v4(float* addr, float4 v) {
    asm volatile("red.global.add.v4.f32 [%0], {%1,%2,%3,%4};"
                 :: "l"(addr), "f"(v.x), "f"(v.y), "f"(v.z), "f"(v.w) : "memory");
}
__device__ __forceinline__ void cp16(uint32_t saddr, const void* g) {
    asm volatile("cp.async.cg.shared.global [%0], [%1], 16;"
                 :: "r"(saddr), "l"(g) : "memory");
}
__device__ __forceinline__ void cp_commit() {
    asm volatile("cp.async.commit_group;" ::: "memory");
}
__device__ __forceinline__ void cp_wait0() {
    asm volatile("cp.async.wait_group 0;" ::: "memory");
}
__device__ __forceinline__ void l2_prefetch(const float* p) {
    asm volatile("prefetch.global.L2 [%0];" :: "l"(p));
}
// mma.sync m16n8k8 tf32 (baseline PTX, sm_80+)
__device__ __forceinline__ void mma_tf32(float d[4], const uint32_t a[4],
                                         uint32_t b0, uint32_t b1) {
    asm volatile(
        "mma.sync.aligned.m16n8k8.row.col.f32.tf32.tf32.f32 "
        "{%0,%1,%2,%3}, {%4,%5,%6,%7}, {%8,%9}, {%0,%1,%2,%3};"
        : "+f"(d[0]), "+f"(d[1]), "+f"(d[2]), "+f"(d[3])
        : "r"(a[0]), "r"(a[1]), "r"(a[2]), "r"(a[3]), "r"(b0), "r"(b1));
}
__device__ __forceinline__ void ldsm_x4(uint32_t a[4], uint32_t saddr) {
    asm volatile("ldmatrix.sync.aligned.m8n8.x4.shared.b16 {%0,%1,%2,%3}, [%4];"
                 : "=r"(a[0]), "=r"(a[1]), "=r"(a[2]), "=r"(a[3]) : "r"(saddr));
}

// ---------------------------------------------------------------------------
// node linear: h = x @ Wl + bl via tf32 mma (unchanged, proven)
// ---------------------------------------------------------------------------
#define NL_LDX 132
#define NL_SMEM_BYTES (128 * NL_LDX * 4)

__global__ void __launch_bounds__(256)
node_linear_mma(const float* __restrict__ x, const float* __restrict__ Wl,
                const float* __restrict__ bl, float* __restrict__ h) {
    extern __shared__ float s_x[];
    const int tid = threadIdx.x;
    const int wid = tid >> 5, lane = tid & 31;
    const int qr = lane >> 2, tig = lane & 3;
    const int nb = wid * 16;
    const int m0 = blockIdx.x * 128;
    const uint32_t sx_u32 = smem_u32(s_x);
    const uint32_t a_off = ((lane & 15) * NL_LDX + ((lane >> 4) << 2)) * 4u;

    uint32_t wf[16][2][2];
#pragma unroll
    for (int ks = 0; ks < 16; ks++)
#pragma unroll
        for (int nt = 0; nt < 2; nt++) {
            int n = nb + nt * 8 + qr;
            wf[ks][nt][0] = tf32_bits(Wl[(size_t)(ks * 8 + tig) * OUT_CH + n]);
            wf[ks][nt][1] = tf32_bits(Wl[(size_t)(ks * 8 + tig + 4) * OUT_CH + n]);
        }
    float bias[4];
#pragma unroll
    for (int nt = 0; nt < 2; nt++)
#pragma unroll
        for (int p = 0; p < 2; p++)
            bias[nt * 2 + p] = bl[nb + nt * 8 + tig * 2 + p];

    for (int i = tid; i < 128 * 32; i += 256) {
        int r = i >> 5, q = i & 31;
        float4 v = make_float4(0.f, 0.f, 0.f, 0.f);
        if (m0 + r < N_NODES)
            v = *(const float4*)(x + (size_t)(m0 + r) * IN_CH + q * 4);
        v.x = rnd_tf32(v.x); v.y = rnd_tf32(v.y);
        v.z = rnd_tf32(v.z); v.w = rnd_tf32(v.w);
        *(float4*)(s_x + r * NL_LDX + q * 4) = v;
    }
    __syncthreads();

    float acc[16][4];
#pragma unroll
    for (int mt = 0; mt < 8; mt++)
#pragma unroll
        for (int nt = 0; nt < 2; nt++) {
            acc[mt * 2 + nt][0] = bias[nt * 2];
            acc[mt * 2 + nt][1] = bias[nt * 2 + 1];
            acc[mt * 2 + nt][2] = bias[nt * 2];
            acc[mt * 2 + nt][3] = bias[nt * 2 + 1];
        }
#pragma unroll
    for (int ks = 0; ks < 16; ks++) {
#pragma unroll
        for (int mt = 0; mt < 8; mt++) {
            uint32_t a[4];
            ldsm_x4(a, sx_u32 + (uint32_t)(mt * 16 * NL_LDX + ks * 8) * 4u + a_off);
            mma_tf32(acc[mt * 2 + 0], a, wf[ks][0][0], wf[ks][0][1]);
            mma_tf32(acc[mt * 2 + 1], a, wf[ks][1][0], wf[ks][1][1]);
        }
    }
#pragma unroll
    for (int mt = 0; mt < 8; mt++)
#pragma unroll
        for (int nt = 0; nt < 2; nt++) {
            int col = nb + nt * 8 + tig * 2;
            int r0 = m0 + mt * 16 + qr;
            float* a = acc[mt * 2 + nt];
            if (r0 < N_NODES)
                *(float2*)(h + (size_t)r0 * OUT_CH + col) = make_float2(a[0], a[1]);
            if (r0 + 8 < N_NODES)
                *(float2*)(h + (size_t)(r0 + 8) * OUT_CH + col) = make_float2(a[2], a[3]);
        }
}

// ---------------------------------------------------------------------------
// WARP-AUTONOMOUS edge kernel: each warp owns a 16-edge tile stream.
// No CTA barriers in the main loop. W1/W2 as shared read-only fragment
// images; per-warp private rbf strip and H/OUT strip.
//
// smem (floats): W1 img 8192 | W2 img 16384 | b1 128 | b2 128 |
//                rbf strips 8x1088 | H/OUT strips 8x2112   = 50432 (201.7 KB)
// ---------------------------------------------------------------------------
#define LDR 68
#define LDH 132
#define S_W1  0
#define S_W2  8192
#define S_B1  24576
#define S_B2  24704
#define S_RBF 24832
#define S_HO  33536
#define SM_FLOATS 50432
#define SM_BYTES (SM_FLOATS * 4)

__global__ void __launch_bounds__(256, 1)
edge_kernel_wa(const float* __restrict__ rbf, const int* __restrict__ eidx,
               const float* __restrict__ W1, const float* __restrict__ b1g,
               const float* __restrict__ W2, const float* __restrict__ b2g,
               const float* __restrict__ h, float* __restrict__ out,
               int n_ctas) {
    extern __shared__ float sm[];
    const uint32_t sbase = smem_u32(sm);
    uint2* w1s  = (uint2*)(sm + S_W1);
    uint2* w2s  = (uint2*)(sm + S_W2);
    float* s_b1 = sm + S_B1;
    float* s_b2 = sm + S_B2;

    const int tid  = threadIdx.x;
    const int wid  = tid >> 5, lane = tid & 31;
    const int qr   = lane >> 2, tig = lane & 3;

    // ---- one-time: build W fragment images + biases (CTA-wide) ----
    for (int i = tid; i < 8 * 16 * 32; i += 256) {
        int ks = i >> 9, r = (i >> 5) & 15, ln = i & 31;
        int tg = ln & 3, q = ln >> 2;
        int k0 = ks * 8 + tg, n = r * 8 + q;
        w1s[i] = make_uint2(tf32_bits(W1[(size_t)k0 * OUT_CH + n]),
                            tf32_bits(W1[(size_t)(k0 + 4) * OUT_CH + n]));
    }
    for (int i = tid; i < 16 * 16 * 32; i += 256) {
        int ks = i >> 9, r = (i >> 5) & 15, ln = i & 31;
        int tg = ln & 3, q = ln >> 2;
        int k0 = ks * 8 + tg, n = r * 8 + q;
        w2s[i] = make_uint2(tf32_bits(W2[(size_t)k0 * OUT_CH + n]),
                            tf32_bits(W2[(size_t)(k0 + 4) * OUT_CH + n]));
    }
    if (tid < 128) { s_b1[tid] = b1g[tid]; s_b2[tid] = b2g[tid]; }
    __syncthreads();     // ONLY CTA barrier: W images ready; warps now diverge.

    // per-warp private strips
    float* strip_ho = sm + S_HO + wid * (16 * LDH);
    const uint32_t rbf_u32 = sbase + (uint32_t)(S_RBF + wid * (16 * LDR)) * 4u;
    const uint32_t ho_u32  = sbase + (uint32_t)(S_HO + wid * (16 * LDH)) * 4u;
    const uint32_t aoff_r = ((lane & 15) * LDR + ((lane >> 4) << 2)) * 4u;
    const uint32_t aoff_h = ((lane & 15) * LDH + ((lane >> 4) << 2)) * 4u;

    const int gw   = blockIdx.x * 8 + wid;   // global warp id
    const int step = n_ctas * 8;

    for (int tile = gw; tile < NT16; tile += step) {
        const size_t e0 = (size_t)tile * TILE16;

        // indices in one reg/lane: lane<16 -> dst[lane], lane>=16 -> src[lane-16]
        int idxreg = (lane < 16) ? eidx[e0 + lane]
                                 : eidx[(size_t)N_EDGES + e0 + (lane - 16)];

        // rbf strip: 16 rows x 64 floats = 256 cp16 chunks; 8 per lane.
        // (R10 bug: only 2/lane -> K=16..63 stale. Now lane pair covers a row.)
        {
            int r = lane >> 1, qb = (lane & 1) * 8;
            const float* grow = rbf + (e0 + r) * NUM_RBF;
            uint32_t srow = rbf_u32 + (uint32_t)(r * LDR) * 4u;
#pragma unroll
            for (int j = 0; j < 8; j++)
                cp16(srow + (uint32_t)((qb + j) * 4) * 4u, grow + (qb + j) * 4);
        }
        cp_commit();

        // L2-prefetch h rows for this tile (hidden behind the 2 GEMMs)
        {
            int e = lane >> 1;
            int srow = __shfl_sync(0xffffffffu, idxreg, 16 + e);
            const float* p = h + (size_t)srow * OUT_CH + (lane & 1) * 64;
            l2_prefetch(p);
            l2_prefetch(p + 32);
        }
        cp_wait0();
        __syncwarp();

        // ---- GEMM1: H = relu(RBF @ W1 + b1); M=16, N=128, K=64 ----
        float acc[16][4];
#pragma unroll
        for (int nt = 0; nt < 16; nt++)
#pragma unroll
            for (int q = 0; q < 4; q++) acc[nt][q] = 0.f;
#pragma unroll
        for (int ks = 0; ks < 8; ks++) {
            uint32_t a[4];
            ldsm_x4(a, rbf_u32 + (uint32_t)(ks * 8) * 4u + aoff_r);
#pragma unroll
            for (int nt = 0; nt < 16; nt++) {
                uint2 b = w1s[(ks * 16 + nt) * 32 + lane];
                mma_tf32(acc[nt], a, b.x, b.y);
            }
        }
        // epilogue1 -> H strip (bias, relu, tf32-round)
#pragma unroll
        for (int nt = 0; nt < 16; nt++) {
            int col = nt * 8 + tig * 2;
            float2 bz = *(const float2*)(s_b1 + col);
            *(float2*)(strip_ho + qr * LDH + col) =
                make_float2(rnd_tf32(fmaxf(acc[nt][0] + bz.x, 0.f)),
                            rnd_tf32(fmaxf(acc[nt][1] + bz.y, 0.f)));
            *(float2*)(strip_ho + (qr + 8) * LDH + col) =
                make_float2(rnd_tf32(fmaxf(acc[nt][2] + bz.x, 0.f)),
                            rnd_tf32(fmaxf(acc[nt][3] + bz.y, 0.f)));
        }
        __syncwarp();

        // ---- GEMM2: Wt = H @ W2 + b2; M=16, N=128, K=128 ----
#pragma unroll
        for (int nt = 0; nt < 16; nt++)
#pragma unroll
            for (int q = 0; q < 4; q++) acc[nt][q] = 0.f;
#pragma unroll
        for (int ks = 0; ks < 16; ks++) {
            uint32_t a[4];
            ldsm_x4(a, ho_u32 + (uint32_t)(ks * 8) * 4u + aoff_h);
#pragma unroll
            for (int nt = 0; nt < 16; nt++) {
                uint2 b = w2s[(ks * 16 + nt) * 32 + lane];
                mma_tf32(acc[nt], a, b.x, b.y);
            }
        }
        __syncwarp();    // all lanes done reading H before overwrite

        // epilogue2 -> OUT strip (overwrites H)
#pragma unroll
        for (int nt = 0; nt < 16; nt++) {
            int col = nt * 8 + tig * 2;
            float2 bz = *(const float2*)(s_b2 + col);
            *(float2*)(strip_ho + qr * LDH + col) =
                make_float2(acc[nt][0] + bz.x, acc[nt][1] + bz.y);
            *(float2*)(strip_ho + (qr + 8) * LDH + col) =
                make_float2(acc[nt][2] + bz.x, acc[nt][3] + bz.y);
        }
        __syncwarp();

        // ---- phase3: gather h[src], modulate, red.v4 scatter (4-deep batches)
#pragma unroll
        for (int b4 = 0; b4 < 4; b4++) {
            float4 hv[4];
            int dst4[4];
#pragma unroll
            for (int u = 0; u < 4; u++) {
                int e = b4 * 4 + u;
                int srow = __shfl_sync(0xffffffffu, idxreg, 16 + e);
                dst4[u]  = __shfl_sync(0xffffffffu, idxreg, e);
                hv[u] = *(const float4*)(h + (size_t)srow * OUT_CH + lane * 4);
            }
#pragma unroll
            for (int u = 0; u < 4; u++) {
                int e = b4 * 4 + u;
                float4 wv = *(const float4*)(strip_ho + e * LDH + lane * 4);
                red_add_v4(out + (size_t)dst4[u] * OUT_CH + lane * 4,
                           make_float4(hv[u].x * wv.x, hv[u].y * wv.y,
                                       hv[u].z * wv.z, hv[u].w * wv.w));
            }
        }
        __syncwarp();    // strip/rbf reuse safety for next tile (warp-private)
    }
}

// ---------------------------------------------------------------------------
extern "C" void kernel_launch(void* const* d_in, const int* in_sizes, int n_in,
                              void* d_out, int out_size) {
    const float* x    = (const float*)d_in[0];
    const int*   eidx = (const int*)d_in[1];
    const float* rbf  = (const float*)d_in[2];
    const float* W1   = (const float*)d_in[3];
    const float* b1   = (const float*)d_in[4];
    const float* W2   = (const float*)d_in[5];
    const float* b2   = (const float*)d_in[6];
    const float* Wl   = (const float*)d_in[7];
    const float* bl   = (const float*)d_in[8];
    float* out = (float*)d_out;

    static float* h_ptr = nullptr;
    static int n_sms = 0;
    if (!h_ptr) {
        cudaGetSymbolAddress((void**)&h_ptr, g_h);
        cudaDeviceGetAttribute(&n_sms, cudaDevAttrMultiProcessorCount, 0);
        cudaFuncSetAttribute(edge_kernel_wa,
                             cudaFuncAttributeMaxDynamicSharedMemorySize, SM_BYTES);
        cudaFuncSetAttribute(node_linear_mma,
                             cudaFuncAttributeMaxDynamicSharedMemorySize, NL_SMEM_BYTES);
    }

    cudaMemsetAsync(d_out, 0, (size_t)N_NODES * OUT_CH * sizeof(float), 0);
    node_linear_mma<<<(N_NODES + 127) / 128, 256, NL_SMEM_BYTES>>>(x, Wl, bl, h_ptr);
    edge_kernel_wa<<<n_sms, 256, SM_BYTES>>>(rbf, eidx, W1, b1, W2, b2,
                                             h_ptr, out, n_sms);
}

// round 12
// speedup vs baseline: 1.0727x; 1.0727x over previous
#include <cuda_runtime.h>
#include <cstdint>

#define N_NODES 40000
#define N_EDGES 640000
#define IN_CH   128
#define OUT_CH  128
#define NUM_RBF 64
#define TILE    128
#define N_TILES (N_EDGES / TILE)

// ---------------- device scratch (no allocs allowed) ----------------
__device__ float g_h[(size_t)N_NODES * OUT_CH];      // x @ Wl + bl

// ---------------- helpers ----------------
__device__ __forceinline__ float rnd_tf32(float x) {
    float r;
    asm("cvt.rna.tf32.f32 %0, %1;" : "=f"(r) : "f"(x));
    return r;
}
__device__ __forceinline__ uint32_t tf32_bits(float x) {
    return __float_as_uint(rnd_tf32(x));
}
__device__ __forceinline__ uint32_t smem_u32(const void* p) {
    uint32_t a;
    asm("{ .reg .u64 t; cvta.to.shared.u64 t, %1; cvt.u32.u64 %0, t; }"
        : "=r"(a) : "l"(p));
    return a;
}
__device__ __forceinline__ void red_add_v4(float* addr, float4 v) {
    asm volatile("red.global.add.v4.f32 [%0], {%1,%2,%3,%4};"
                 :: "l"(addr), "f"(v.x), "f"(v.y), "f"(v.z), "f"(v.w) : "memory");
}
__device__ __forceinline__ void cp16(uint32_t saddr, const void* g) {
    asm volatile("cp.async.cg.shared.global [%0], [%1], 16;"
                 :: "r"(saddr), "l"(g) : "memory");
}
__device__ __forceinline__ void cp_commit() {
    asm volatile("cp.async.commit_group;" ::: "memory");
}
__device__ __forceinline__ void cp_wait1() {
    asm volatile("cp.async.wait_group 1;" ::: "memory");
}
__device__ __forceinline__ void l2_prefetch(const float* p) {
    asm volatile("prefetch.global.L2 [%0];" :: "l"(p));
}
// mma.sync m16n8k8 tf32 (baseline PTX, sm_80+)
__device__ __forceinline__ void mma_tf32(float d[4], const uint32_t a[4],
                                         uint32_t b0, uint32_t b1) {
    asm volatile(
        "mma.sync.aligned.m16n8k8.row.col.f32.tf32.tf32.f32 "
        "{%0,%1,%2,%3}, {%4,%5,%6,%7}, {%8,%9}, {%0,%1,%2,%3};"
        : "+f"(d[0]), "+f"(d[1]), "+f"(d[2]), "+f"(d[3])
        : "r"(a[0]), "r"(a[1]), "r"(a[2]), "r"(a[3]), "r"(b0), "r"(b1));
}
__device__ __forceinline__ void ldsm_x4(uint32_t a[4], uint32_t saddr) {
    asm volatile("ldmatrix.sync.aligned.m8n8.x4.shared.b16 {%0,%1,%2,%3}, [%4];"
                 : "=r"(a[0]), "=r"(a[1]), "=r"(a[2]), "=r"(a[3]) : "r"(saddr));
}

// ---------------------------------------------------------------------------
// node linear: h = x @ Wl + bl via tf32 mma (unchanged, proven)
// ---------------------------------------------------------------------------
#define NL_LDX 132
#define NL_SMEM_BYTES (128 * NL_LDX * 4)

__global__ void __launch_bounds__(256)
node_linear_mma(const float* __restrict__ x, const float* __restrict__ Wl,
                const float* __restrict__ bl, float* __restrict__ h) {
    extern __shared__ float s_x[];
    const int tid = threadIdx.x;
    const int wid = tid >> 5, lane = tid & 31;
    const int qr = lane >> 2, tig = lane & 3;
    const int nb = wid * 16;
    const int m0 = blockIdx.x * 128;
    const uint32_t sx_u32 = smem_u32(s_x);
    const uint32_t a_off = ((lane & 15) * NL_LDX + ((lane >> 4) << 2)) * 4u;

    uint32_t wf[16][2][2];
#pragma unroll
    for (int ks = 0; ks < 16; ks++)
#pragma unroll
        for (int nt = 0; nt < 2; nt++) {
            int n = nb + nt * 8 + qr;
            wf[ks][nt][0] = tf32_bits(Wl[(size_t)(ks * 8 + tig) * OUT_CH + n]);
            wf[ks][nt][1] = tf32_bits(Wl[(size_t)(ks * 8 + tig + 4) * OUT_CH + n]);
        }
    float bias[4];
#pragma unroll
    for (int nt = 0; nt < 2; nt++)
#pragma unroll
        for (int p = 0; p < 2; p++)
            bias[nt * 2 + p] = bl[nb + nt * 8 + tig * 2 + p];

    for (int i = tid; i < 128 * 32; i += 256) {
        int r = i >> 5, q = i & 31;
        float4 v = make_float4(0.f, 0.f, 0.f, 0.f);
        if (m0 + r < N_NODES)
            v = *(const float4*)(x + (size_t)(m0 + r) * IN_CH + q * 4);
        v.x = rnd_tf32(v.x); v.y = rnd_tf32(v.y);
        v.z = rnd_tf32(v.z); v.w = rnd_tf32(v.w);
        *(float4*)(s_x + r * NL_LDX + q * 4) = v;
    }
    __syncthreads();

    float acc[16][4];
#pragma unroll
    for (int mt = 0; mt < 8; mt++)
#pragma unroll
        for (int nt = 0; nt < 2; nt++) {
            acc[mt * 2 + nt][0] = bias[nt * 2];
            acc[mt * 2 + nt][1] = bias[nt * 2 + 1];
            acc[mt * 2 + nt][2] = bias[nt * 2];
            acc[mt * 2 + nt][3] = bias[nt * 2 + 1];
        }
#pragma unroll
    for (int ks = 0; ks < 16; ks++) {
#pragma unroll
        for (int mt = 0; mt < 8; mt++) {
            uint32_t a[4];
            ldsm_x4(a, sx_u32 + (uint32_t)(mt * 16 * NL_LDX + ks * 8) * 4u + a_off);
            mma_tf32(acc[mt * 2 + 0], a, wf[ks][0][0], wf[ks][0][1]);
            mma_tf32(acc[mt * 2 + 1], a, wf[ks][1][0], wf[ks][1][1]);
        }
    }
#pragma unroll
    for (int mt = 0; mt < 8; mt++)
#pragma unroll
        for (int nt = 0; nt < 2; nt++) {
            int col = nb + nt * 8 + tig * 2;
            int r0 = m0 + mt * 16 + qr;
            float* a = acc[mt * 2 + nt];
            if (r0 < N_NODES)
                *(float2*)(h + (size_t)r0 * OUT_CH + col) = make_float2(a[0], a[1]);
            if (r0 + 8 < N_NODES)
                *(float2*)(h + (size_t)(r0 + 8) * OUT_CH + col) = make_float2(a[2], a[3]);
        }
}

// ---------------------------------------------------------------------------
// persistent edge kernel: 512 threads (16 warps = 4/SMSP), regs capped 128.
//   GEMM1: 2M x 8N (warp M=64, N=16), b1f in regs (32)
//   GEMM2: 4M x 4N (warp M=32, N=32), b2f from smem W2-fragment image
//   single H/OUT buffer; cp.async double-buffered rbf/idx
// smem floats: W2img 16384 | rbf 2x8704 | H/OUT 16896 | idx 2x256 | b 256
//   = 51456 floats = 205,824 B
// ---------------------------------------------------------------------------
#define LDR 68
#define LDH 132
#define S_W2   0
#define S_RBF0 16384
#define S_RBF1 25088
#define S_HO   33792
#define S_IDX0 50688
#define S_IDX1 50944
#define S_B1   51200
#define S_B2   51328
#define SM_FLOATS 51456
#define SM_BYTES (SM_FLOATS * 4)

__device__ __forceinline__ void prefetch_tile(uint32_t sb, int buf,
                                              const float* __restrict__ rbf,
                                              const int* __restrict__ eidx,
                                              int tile, int tid) {
    const size_t e0 = (size_t)tile * TILE;
    const uint32_t rb = sb + (uint32_t)(S_RBF0 + buf * 8704) * 4u;
#pragma unroll
    for (int i = tid; i < 2048; i += 512) {
        int r = i >> 4, q = i & 15;
        cp16(rb + (uint32_t)(r * LDR + q * 4) * 4u,
             rbf + (e0 + r) * NUM_RBF + q * 4);
    }
    const uint32_t ib = sb + (uint32_t)(S_IDX0 + buf * 256) * 4u;
    if (tid < 32)
        cp16(ib + tid * 16u, eidx + e0 + tid * 4);
    else if (tid < 64)
        cp16(ib + 512u + (tid - 32) * 16u,
             eidx + (size_t)N_EDGES + e0 + (tid - 32) * 4);
}

__global__ void __launch_bounds__(512, 1)
edge_kernel_512(const float* __restrict__ rbf, const int* __restrict__ eidx,
                const float* __restrict__ W1, const float* __restrict__ b1g,
                const float* __restrict__ W2, const float* __restrict__ b2g,
                const float* __restrict__ h, float* __restrict__ out,
                int n_ctas) {
    extern __shared__ float sm[];
    const uint32_t sbase = smem_u32(sm);
    uint2* w2s   = (uint2*)(sm + S_W2);
    float* s_HO  = sm + S_HO;
    float* s_b1  = sm + S_B1;
    float* s_b2  = sm + S_B2;

    const int tid  = threadIdx.x;
    const int wid  = tid >> 5, lane = tid & 31;
    const int qr   = lane >> 2, tig = lane & 3;
    // GEMM1 mapping: 2M x 8N
    const int mg1  = wid >> 3;           // 0..1 -> rows mg1*64..
    const int ng1  = wid & 7;            // 0..7 -> cols ng1*16..
    // GEMM2 mapping: 4M x 4N
    const int mg2  = wid >> 2;           // 0..3 -> rows mg2*32..
    const int ng2  = wid & 3;            // 0..3 -> cols ng2*32..

    const uint32_t aoff_r = ((lane & 15) * LDR + ((lane >> 4) << 2)) * 4u;
    const uint32_t aoff_h = ((lane & 15) * LDH + ((lane >> 4) << 2)) * 4u;
    const uint32_t sHO_u32 = sbase + (uint32_t)S_HO * 4u;

    // ---- one-time: W2 fragment image (proven R9 layout), b1f regs, biases
    for (int i = tid; i < 16 * 16 * 32; i += 512) {
        int ks = i >> 9, r = (i >> 5) & 15, ln = i & 31;
        int tg = ln & 3, q = ln >> 2;
        int k0 = ks * 8 + tg, n = r * 8 + q;
        w2s[i] = make_uint2(tf32_bits(W2[(size_t)k0 * OUT_CH + n]),
                            tf32_bits(W2[(size_t)(k0 + 4) * OUT_CH + n]));
    }
    uint32_t b1f[8][2][2];               // 32 regs
#pragma unroll
    for (int ks = 0; ks < 8; ks++)
#pragma unroll
        for (int nt = 0; nt < 2; nt++) {
            int n = ng1 * 16 + nt * 8 + qr;
            b1f[ks][nt][0] = tf32_bits(W1[(size_t)(ks * 8 + tig) * OUT_CH + n]);
            b1f[ks][nt][1] = tf32_bits(W1[(size_t)(ks * 8 + tig + 4) * OUT_CH + n]);
        }
    if (tid < 128) { s_b1[tid] = b1g[tid]; s_b2[tid] = b2g[tid]; }

    int buf = 0;
    prefetch_tile(sbase, 0, rbf, eidx, blockIdx.x, tid);
    cp_commit();

    for (int tile = blockIdx.x; tile < N_TILES; tile += n_ctas) {
        int nx = tile + n_ctas;
        if (nx >= N_TILES) nx = tile;
        prefetch_tile(sbase, buf ^ 1, rbf, eidx, nx, tid);
        cp_commit();
        cp_wait1();
        __syncthreads();   // also orders one-time init on iter 0

        const uint32_t sR = sbase + (uint32_t)(S_RBF0 + buf * 8704) * 4u;
        int* s_dst = (int*)(sm + S_IDX0 + buf * 256);
        int* s_src = s_dst + 128;

        // L2-prefetch this tile's h rows (hidden behind both GEMMs)
        {
            int e = tid >> 2;
            l2_prefetch(h + (size_t)s_src[e] * OUT_CH + (tid & 3) * 32);
        }

        // ---- GEMM1: H = relu(RBF @ W1 + b1); warp M=64 x N=16, K=64 ----
        {
            float acc[4][2][4];          // 32 regs
#pragma unroll
            for (int mt = 0; mt < 4; mt++)
#pragma unroll
                for (int nt = 0; nt < 2; nt++)
#pragma unroll
                    for (int q = 0; q < 4; q++) acc[mt][nt][q] = 0.f;
#pragma unroll
            for (int ks = 0; ks < 8; ks++)
#pragma unroll
                for (int mt = 0; mt < 4; mt++) {
                    uint32_t a[4];
                    ldsm_x4(a, sR + (uint32_t)((mg1 * 64 + mt * 16) * LDR + ks * 8) * 4u + aoff_r);
                    mma_tf32(acc[mt][0], a, b1f[ks][0][0], b1f[ks][0][1]);
                    mma_tf32(acc[mt][1], a, b1f[ks][1][0], b1f[ks][1][1]);
                }
#pragma unroll
            for (int nt = 0; nt < 2; nt++) {
                int col = ng1 * 16 + nt * 8 + tig * 2;
                float2 bz = *(const float2*)(s_b1 + col);
#pragma unroll
                for (int mt = 0; mt < 4; mt++) {
                    int r0 = mg1 * 64 + mt * 16 + qr;
                    float* a = acc[mt][nt];
                    *(float2*)(s_HO + r0 * LDH + col) =
                        make_float2(rnd_tf32(fmaxf(a[0] + bz.x, 0.f)),
                                    rnd_tf32(fmaxf(a[1] + bz.y, 0.f)));
                    *(float2*)(s_HO + (r0 + 8) * LDH + col) =
                        make_float2(rnd_tf32(fmaxf(a[2] + bz.x, 0.f)),
                                    rnd_tf32(fmaxf(a[3] + bz.y, 0.f)));
                }
            }
        }
        __syncthreads();

        // ---- GEMM2: Wt = H @ W2 + b2; warp M=32 x N=32, K=128 ----
        {
            float acc[2][4][4];          // 32 regs
#pragma unroll
            for (int mt = 0; mt < 2; mt++)
#pragma unroll
                for (int n8 = 0; n8 < 4; n8++)
#pragma unroll
                    for (int q = 0; q < 4; q++) acc[mt][n8][q] = 0.f;
#pragma unroll
            for (int ks = 0; ks < 16; ks++) {
                uint32_t a0[4], a1[4];
                ldsm_x4(a0, sHO_u32 + (uint32_t)((mg2 * 32 + 0) * LDH + ks * 8) * 4u + aoff_h);
                ldsm_x4(a1, sHO_u32 + (uint32_t)((mg2 * 32 + 16) * LDH + ks * 8) * 4u + aoff_h);
#pragma unroll
                for (int n8 = 0; n8 < 4; n8++) {
                    uint2 b = w2s[(ks * 16 + ng2 * 4 + n8) * 32 + lane];
                    mma_tf32(acc[0][n8], a0, b.x, b.y);
                    mma_tf32(acc[1][n8], a1, b.x, b.y);
                }
            }
            __syncthreads();   // all H reads done before overwrite
#pragma unroll
            for (int n8 = 0; n8 < 4; n8++) {
                int col = ng2 * 32 + n8 * 8 + tig * 2;
                float2 bz = *(const float2*)(s_b2 + col);
#pragma unroll
                for (int mt = 0; mt < 2; mt++) {
                    int r0 = mg2 * 32 + mt * 16 + qr;
                    float* a = acc[mt][n8];
                    *(float2*)(s_HO + r0 * LDH + col) =
                        make_float2(a[0] + bz.x, a[1] + bz.y);
                    *(float2*)(s_HO + (r0 + 8) * LDH + col) =
                        make_float2(a[2] + bz.x, a[3] + bz.y);
                }
            }
        }
        __syncthreads();

        // ---- phase3: 16 warps x 8 edges; batched gather, red.v4 scatter ----
#pragma unroll
        for (int half = 0; half < 2; half++) {
            float4 hv[4];
            int dst4[4];
#pragma unroll
            for (int u = 0; u < 4; u++) {
                int e = wid * 8 + half * 4 + u;
                dst4[u] = s_dst[e];
                hv[u] = *(const float4*)(h + (size_t)s_src[e] * OUT_CH + lane * 4);
            }
#pragma unroll
            for (int u = 0; u < 4; u++) {
                int e = wid * 8 + half * 4 + u;
                float4 wv = *(const float4*)(s_HO + e * LDH + lane * 4);
                red_add_v4(out + (size_t)dst4[u] * OUT_CH + lane * 4,
                           make_float4(hv[u].x * wv.x, hv[u].y * wv.y,
                                       hv[u].z * wv.z, hv[u].w * wv.w));
            }
        }
        // Race guard (R6 lesson): next prefetch overwrites this buffer's
        // rbf/idx; all warps must finish reading first.
        __syncthreads();
        buf ^= 1;
    }
}

// ---------------------------------------------------------------------------
extern "C" void kernel_launch(void* const* d_in, const int* in_sizes, int n_in,
                              void* d_out, int out_size) {
    const float* x    = (const float*)d_in[0];
    const int*   eidx = (const int*)d_in[1];
    const float* rbf  = (const float*)d_in[2];
    const float* W1   = (const float*)d_in[3];
    const float* b1   = (const float*)d_in[4];
    const float* W2   = (const float*)d_in[5];
    const float* b2   = (const float*)d_in[6];
    const float* Wl   = (const float*)d_in[7];
    const float* bl   = (const float*)d_in[8];
    float* out = (float*)d_out;

    static float* h_ptr = nullptr;
    static int n_sms = 0;
    if (!h_ptr) {
        cudaGetSymbolAddress((void**)&h_ptr, g_h);
        cudaDeviceGetAttribute(&n_sms, cudaDevAttrMultiProcessorCount, 0);
        cudaFuncSetAttribute(edge_kernel_512,
                             cudaFuncAttributeMaxDynamicSharedMemorySize, SM_BYTES);
        cudaFuncSetAttribute(node_linear_mma,
                             cudaFuncAttributeMaxDynamicSharedMemorySize, NL_SMEM_BYTES);
    }

    cudaMemsetAsync(d_out, 0, (size_t)N_NODES * OUT_CH * sizeof(float), 0);
    node_linear_mma<<<(N_NODES + 127) / 128, 256, NL_SMEM_BYTES>>>(x, Wl, bl, h_ptr);
    edge_kernel_512<<<n_sms, 512, SM_BYTES>>>(rbf, eidx, W1, b1, W2, b2,
                                              h_ptr, out, n_sms);
}

// round 13
// speedup vs baseline: 1.2139x; 1.1316x over previous
#include <cuda_runtime.h>
#include <cstdint>

#define N_NODES 40000
#define N_EDGES 640000
#define IN_CH   128
#define OUT_CH  128
#define NUM_RBF 64
#define TILE64  64
#define NT64    (N_EDGES / TILE64)     // 10000

// ---------------- device scratch (no allocs allowed) ----------------
__device__ float g_h[(size_t)N_NODES * OUT_CH];      // x @ Wl + bl

// ---------------- helpers ----------------
__device__ __forceinline__ float rnd_tf32(float x) {
    float r;
    asm("cvt.rna.tf32.f32 %0, %1;" : "=f"(r) : "f"(x));
    return r;
}
__device__ __forceinline__ uint32_t tf32_bits(float x) {
    return __float_as_uint(rnd_tf32(x));
}
__device__ __forceinline__ uint32_t smem_u32(const void* p) {
    uint32_t a;
    asm("{ .reg .u64 t; cvta.to.shared.u64 t, %1; cvt.u32.u64 %0, t; }"
        : "=r"(a) : "l"(p));
    return a;
}
__device__ __forceinline__ void red_add_v4(float* addr, float4 v) {
    asm volatile("red.global.add.v4.f32 [%0], {%1,%2,%3,%4};"
                 :: "l"(addr), "f"(v.x), "f"(v.y), "f"(v.z), "f"(v.w) : "memory");
}
__device__ __forceinline__ void cp16(uint32_t saddr, const void* g) {
    asm volatile("cp.async.cg.shared.global [%0], [%1], 16;"
                 :: "r"(saddr), "l"(g) : "memory");
}
__device__ __forceinline__ void cp_commit() {
    asm volatile("cp.async.commit_group;" ::: "memory");
}
__device__ __forceinline__ void cp_wait0() {
    asm volatile("cp.async.wait_group 0;" ::: "memory");
}
__device__ __forceinline__ void bar_compute() {       // warps 0-7 only
    asm volatile("bar.sync 1, 256;" ::: "memory");
}
// mma.sync m16n8k8 tf32 (baseline PTX, sm_80+)
__device__ __forceinline__ void mma_tf32(float d[4], const uint32_t a[4],
                                         uint32_t b0, uint32_t b1) {
    asm volatile(
        "mma.sync.aligned.m16n8k8.row.col.f32.tf32.tf32.f32 "
        "{%0,%1,%2,%3}, {%4,%5,%6,%7}, {%8,%9}, {%0,%1,%2,%3};"
        : "+f"(d[0]), "+f"(d[1]), "+f"(d[2]), "+f"(d[3])
        : "r"(a[0]), "r"(a[1]), "r"(a[2]), "r"(a[3]), "r"(b0), "r"(b1));
}
__device__ __forceinline__ void ldsm_x4(uint32_t a[4], uint32_t saddr) {
    asm volatile("ldmatrix.sync.aligned.m8n8.x4.shared.b16 {%0,%1,%2,%3}, [%4];"
                 : "=r"(a[0]), "=r"(a[1]), "=r"(a[2]), "=r"(a[3]) : "r"(saddr));
}

// ---------------------------------------------------------------------------
// node linear: h = x @ Wl + bl via tf32 mma (unchanged, proven)
// ---------------------------------------------------------------------------
#define NL_LDX 132
#define NL_SMEM_BYTES (128 * NL_LDX * 4)

__global__ void __launch_bounds__(256)
node_linear_mma(const float* __restrict__ x, const float* __restrict__ Wl,
                const float* __restrict__ bl, float* __restrict__ h) {
    extern __shared__ float s_x[];
    const int tid = threadIdx.x;
    const int wid = tid >> 5, lane = tid & 31;
    const int qr = lane >> 2, tig = lane & 3;
    const int nb = wid * 16;
    const int m0 = blockIdx.x * 128;
    const uint32_t sx_u32 = smem_u32(s_x);
    const uint32_t a_off = ((lane & 15) * NL_LDX + ((lane >> 4) << 2)) * 4u;

    uint32_t wf[16][2][2];
#pragma unroll
    for (int ks = 0; ks < 16; ks++)
#pragma unroll
        for (int nt = 0; nt < 2; nt++) {
            int n = nb + nt * 8 + qr;
            wf[ks][nt][0] = tf32_bits(Wl[(size_t)(ks * 8 + tig) * OUT_CH + n]);
            wf[ks][nt][1] = tf32_bits(Wl[(size_t)(ks * 8 + tig + 4) * OUT_CH + n]);
        }
    float bias[4];
#pragma unroll
    for (int nt = 0; nt < 2; nt++)
#pragma unroll
        for (int p = 0; p < 2; p++)
            bias[nt * 2 + p] = bl[nb + nt * 8 + tig * 2 + p];

    for (int i = tid; i < 128 * 32; i += 256) {
        int r = i >> 5, q = i & 31;
        float4 v = make_float4(0.f, 0.f, 0.f, 0.f);
        if (m0 + r < N_NODES)
            v = *(const float4*)(x + (size_t)(m0 + r) * IN_CH + q * 4);
        v.x = rnd_tf32(v.x); v.y = rnd_tf32(v.y);
        v.z = rnd_tf32(v.z); v.w = rnd_tf32(v.w);
        *(float4*)(s_x + r * NL_LDX + q * 4) = v;
    }
    __syncthreads();

    float acc[16][4];
#pragma unroll
    for (int mt = 0; mt < 8; mt++)
#pragma unroll
        for (int nt = 0; nt < 2; nt++) {
            acc[mt * 2 + nt][0] = bias[nt * 2];
            acc[mt * 2 + nt][1] = bias[nt * 2 + 1];
            acc[mt * 2 + nt][2] = bias[nt * 2];
            acc[mt * 2 + nt][3] = bias[nt * 2 + 1];
        }
#pragma unroll
    for (int ks = 0; ks < 16; ks++) {
#pragma unroll
        for (int mt = 0; mt < 8; mt++) {
            uint32_t a[4];
            ldsm_x4(a, sx_u32 + (uint32_t)(mt * 16 * NL_LDX + ks * 8) * 4u + a_off);
            mma_tf32(acc[mt * 2 + 0], a, wf[ks][0][0], wf[ks][0][1]);
            mma_tf32(acc[mt * 2 + 1], a, wf[ks][1][0], wf[ks][1][1]);
        }
    }
#pragma unroll
    for (int mt = 0; mt < 8; mt++)
#pragma unroll
        for (int nt = 0; nt < 2; nt++) {
            int col = nb + nt * 8 + tig * 2;
            int r0 = m0 + mt * 16 + qr;
            float* a = acc[mt * 2 + nt];
            if (r0 < N_NODES)
                *(float2*)(h + (size_t)r0 * OUT_CH + col) = make_float2(a[0], a[1]);
            if (r0 + 8 < N_NODES)
                *(float2*)(h + (size_t)(r0 + 8) * OUT_CH + col) = make_float2(a[2], a[3]);
        }
}

// ---------------------------------------------------------------------------
// WARP-SPECIALIZED edge kernel: 512 threads.
//   warps 0-7  (compute): GEMM1 -> H -> GEMM2 -> OUT[i&1]
//   warps 8-15 (scatter): cp.async rbf prefetch for tile t+1,
//                         gather/modulate/red.v4 for tile t-1 from OUT[(i-1)&1]
// One __syncthreads per iteration pipelines the groups one tile apart.
//
// smem floats: W2img 16384 | rbf 2x4352 | H 8448 | OUT 2x8448 | b1/b2 256
//   = 50688 floats = 202,752 B
// ---------------------------------------------------------------------------
#define LDR 68
#define LDH 132
#define S_W2   0
#define S_RBF0 16384
#define S_RBF1 20736
#define S_H    25088
#define S_OUT0 33536
#define S_OUT1 41984
#define S_B1   50432
#define S_B2   50560
#define SM_FLOATS 50688
#define SM_BYTES (SM_FLOATS * 4)

// rbf prefetch: 64 rows x 64 floats = 1024 cp16 chunks; 256 scatter threads x4
__device__ __forceinline__ void prefetch_rbf(uint32_t sb, int slot,
                                             const float* __restrict__ rbf,
                                             int tile, int tids) {
    const size_t e0 = (size_t)tile * TILE64;
    const uint32_t rb = sb + (uint32_t)(slot ? S_RBF1 : S_RBF0) * 4u;
#pragma unroll
    for (int j = 0; j < 4; j++) {
        int c = j * 256 + tids;
        int r = c >> 4, q = c & 15;
        cp16(rb + (uint32_t)(r * LDR + q * 4) * 4u,
             rbf + (e0 + r) * NUM_RBF + q * 4);
    }
}

__global__ void __launch_bounds__(512, 1)
edge_kernel_ws(const float* __restrict__ rbf, const int* __restrict__ eidx,
               const float* __restrict__ W1, const float* __restrict__ b1g,
               const float* __restrict__ W2, const float* __restrict__ b2g,
               const float* __restrict__ h, float* __restrict__ out,
               int n_ctas) {
    extern __shared__ float sm[];
    const uint32_t sbase = smem_u32(sm);
    uint2* w2s  = (uint2*)(sm + S_W2);
    float* s_H  = sm + S_H;
    float* s_b1 = sm + S_B1;
    float* s_b2 = sm + S_B2;

    const int tid  = threadIdx.x;
    const int wid  = tid >> 5, lane = tid & 31;
    const int qr   = lane >> 2, tig = lane & 3;

    // ---- one-time: W2 fragment image (R9-proven layout) + biases ----
    for (int i = tid; i < 16 * 16 * 32; i += 512) {
        int ks = i >> 9, r = (i >> 5) & 15, ln = i & 31;
        int tg = ln & 3, q = ln >> 2;
        int k0 = ks * 8 + tg, n = r * 8 + q;
        w2s[i] = make_uint2(tf32_bits(W2[(size_t)k0 * OUT_CH + n]),
                            tf32_bits(W2[(size_t)(k0 + 4) * OUT_CH + n]));
    }
    if (tid < 128) { s_b1[tid] = b1g[tid]; s_b2[tid] = b2g[tid]; }

    const int start = blockIdx.x;
    const int step  = n_ctas;

    // compute-warp constants
    const uint32_t aoff_r = ((lane & 15) * LDR + ((lane >> 4) << 2)) * 4u;
    const uint32_t aoff_h = ((lane & 15) * LDH + ((lane >> 4) << 2)) * 4u;
    const uint32_t sH_u32 = sbase + (uint32_t)S_H * 4u;
    uint32_t b1f[8][2][2];
    if (wid < 8) {                      // GEMM1: warp = 1M x 8N (N base wid*16)
        int nb = wid * 16;
#pragma unroll
        for (int ks = 0; ks < 8; ks++)
#pragma unroll
            for (int nt = 0; nt < 2; nt++) {
                int n = nb + nt * 8 + qr;
                b1f[ks][nt][0] = tf32_bits(W1[(size_t)(ks * 8 + tig) * OUT_CH + n]);
                b1f[ks][nt][1] = tf32_bits(W1[(size_t)(ks * 8 + tig + 4) * OUT_CH + n]);
            }
    } else {                            // scatter warps: prologue rbf prefetch
        prefetch_rbf(sbase, 0, rbf, start, tid - 256);
        cp_commit();
        cp_wait0();
    }
    __syncthreads();

    int i = 0;
    int tile = start;
    for (; tile < NT64; tile += step, i++) {
        if (wid < 8) {
            // ================= COMPUTE GROUP =================
            const uint32_t sR = sbase +
                (uint32_t)((i & 1) ? S_RBF1 : S_RBF0) * 4u;
            float* s_out = sm + ((i & 1) ? S_OUT1 : S_OUT0);

            // GEMM1: H = relu(RBF @ W1 + b1); warp M=64 x N=16, K=64
            {
                float acc[4][2][4];
#pragma unroll
                for (int mt = 0; mt < 4; mt++)
#pragma unroll
                    for (int nt = 0; nt < 2; nt++)
#pragma unroll
                        for (int q = 0; q < 4; q++) acc[mt][nt][q] = 0.f;
#pragma unroll
                for (int ks = 0; ks < 8; ks++)
#pragma unroll
                    for (int mt = 0; mt < 4; mt++) {
                        uint32_t a[4];
                        ldsm_x4(a, sR + (uint32_t)(mt * 16 * LDR + ks * 8) * 4u + aoff_r);
                        mma_tf32(acc[mt][0], a, b1f[ks][0][0], b1f[ks][0][1]);
                        mma_tf32(acc[mt][1], a, b1f[ks][1][0], b1f[ks][1][1]);
                    }
                int nb = wid * 16;
#pragma unroll
                for (int nt = 0; nt < 2; nt++) {
                    int col = nb + nt * 8 + tig * 2;
                    float2 bz = *(const float2*)(s_b1 + col);
#pragma unroll
                    for (int mt = 0; mt < 4; mt++) {
                        int r0 = mt * 16 + qr;
                        float* a = acc[mt][nt];
                        *(float2*)(s_H + r0 * LDH + col) =
                            make_float2(rnd_tf32(fmaxf(a[0] + bz.x, 0.f)),
                                        rnd_tf32(fmaxf(a[1] + bz.y, 0.f)));
                        *(float2*)(s_H + (r0 + 8) * LDH + col) =
                            make_float2(rnd_tf32(fmaxf(a[2] + bz.x, 0.f)),
                                        rnd_tf32(fmaxf(a[3] + bz.y, 0.f)));
                    }
                }
            }
            bar_compute();   // H write -> H read

            // GEMM2: Wt = H @ W2 + b2; warp = 2M x 4N (M=32, N=32), K=128
            {
                const int mg = wid >> 2;         // 0..1
                const int ng = wid & 3;          // 0..3
                float acc[2][4][4];
#pragma unroll
                for (int mt = 0; mt < 2; mt++)
#pragma unroll
                    for (int n8 = 0; n8 < 4; n8++)
#pragma unroll
                        for (int q = 0; q < 4; q++) acc[mt][n8][q] = 0.f;
#pragma unroll
                for (int ks = 0; ks < 16; ks++) {
                    uint32_t a0[4], a1[4];
                    ldsm_x4(a0, sH_u32 + (uint32_t)((mg * 32 + 0) * LDH + ks * 8) * 4u + aoff_h);
                    ldsm_x4(a1, sH_u32 + (uint32_t)((mg * 32 + 16) * LDH + ks * 8) * 4u + aoff_h);
#pragma unroll
                    for (int n8 = 0; n8 < 4; n8++) {
                        uint2 b = w2s[(ks * 16 + ng * 4 + n8) * 32 + lane];
                        mma_tf32(acc[0][n8], a0, b.x, b.y);
                        mma_tf32(acc[1][n8], a1, b.x, b.y);
                    }
                }
#pragma unroll
                for (int n8 = 0; n8 < 4; n8++) {
                    int col = ng * 32 + n8 * 8 + tig * 2;
                    float2 bz = *(const float2*)(s_b2 + col);
#pragma unroll
                    for (int mt = 0; mt < 2; mt++) {
                        int r0 = mg * 32 + mt * 16 + qr;
                        float* a = acc[mt][n8];
                        *(float2*)(s_out + r0 * LDH + col) =
                            make_float2(a[0] + bz.x, a[1] + bz.y);
                        *(float2*)(s_out + (r0 + 8) * LDH + col) =
                            make_float2(a[2] + bz.x, a[3] + bz.y);
                    }
                }
            }
        } else {
            // ================= SCATTER GROUP =================
            const int sw = wid - 8;              // 0..7, owns 8 edges
            int nx = tile + step;
            bool pf = (nx < NT64);
            if (pf) {
                prefetch_rbf(sbase, (i & 1) ^ 1, rbf, nx, tid - 256);
                cp_commit();
            }
            if (i > 0) {
                const int p = tile - step;
                float* s_outp = sm + (((i - 1) & 1) ? S_OUT1 : S_OUT0);
                const size_t e0 = (size_t)p * TILE64;
                int e8 = sw * 8 + (lane & 7);
                int dstv = eidx[e0 + e8];
                int srcv = eidx[(size_t)N_EDGES + e0 + e8];
#pragma unroll
                for (int half = 0; half < 2; half++) {
                    float4 hv[4];
                    int d4[4];
#pragma unroll
                    for (int u = 0; u < 4; u++) {
                        int u8 = half * 4 + u;
                        int srow = __shfl_sync(0xffffffffu, srcv, u8);
                        d4[u]    = __shfl_sync(0xffffffffu, dstv, u8);
                        hv[u] = *(const float4*)(h + (size_t)srow * OUT_CH + lane * 4);
                    }
#pragma unroll
                    for (int u = 0; u < 4; u++) {
                        int e = sw * 8 + half * 4 + u;
                        float4 wv = *(const float4*)(s_outp + e * LDH + lane * 4);
                        red_add_v4(out + (size_t)d4[u] * OUT_CH + lane * 4,
                                   make_float4(hv[u].x * wv.x, hv[u].y * wv.y,
                                               hv[u].z * wv.z, hv[u].w * wv.w));
                    }
                }
            }
            if (pf) cp_wait0();
        }
        // pipeline boundary: OUT[i&1] published to scatter; rbf[(i+1)&1] ready
        __syncthreads();
    }

    // ---- drain: scatter the last tile this CTA computed ----
    if (i > 0 && wid >= 8) {
        const int sw = wid - 8;
        const int p = tile - step;               // last computed tile
        float* s_outp = sm + (((i - 1) & 1) ? S_OUT1 : S_OUT0);
        const size_t e0 = (size_t)p * TILE64;
        int e8 = sw * 8 + (lane & 7);
        int dstv = eidx[e0 + e8];
        int srcv = eidx[(size_t)N_EDGES + e0 + e8];
#pragma unroll
        for (int half = 0; half < 2; half++) {
            float4 hv[4];
            int d4[4];
#pragma unroll
            for (int u = 0; u < 4; u++) {
                int u8 = half * 4 + u;
                int srow = __shfl_sync(0xffffffffu, srcv, u8);
                d4[u]    = __shfl_sync(0xffffffffu, dstv, u8);
                hv[u] = *(const float4*)(h + (size_t)srow * OUT_CH + lane * 4);
            }
#pragma unroll
            for (int u = 0; u < 4; u++) {
                int e = sw * 8 + half * 4 + u;
                float4 wv = *(const float4*)(s_outp + e * LDH + lane * 4);
                red_add_v4(out + (size_t)d4[u] * OUT_CH + lane * 4,
                           make_float4(hv[u].x * wv.x, hv[u].y * wv.y,
                                       hv[u].z * wv.z, hv[u].w * wv.w));
            }
        }
    }
}

// ---------------------------------------------------------------------------
extern "C" void kernel_launch(void* const* d_in, const int* in_sizes, int n_in,
                              void* d_out, int out_size) {
    const float* x    = (const float*)d_in[0];
    const int*   eidx = (const int*)d_in[1];
    const float* rbf  = (const float*)d_in[2];
    const float* W1   = (const float*)d_in[3];
    const float* b1   = (const float*)d_in[4];
    const float* W2   = (const float*)d_in[5];
    const float* b2   = (const float*)d_in[6];
    const float* Wl   = (const float*)d_in[7];
    const float* bl   = (const float*)d_in[8];
    float* out = (float*)d_out;

    static float* h_ptr = nullptr;
    static int n_sms = 0;
    if (!h_ptr) {
        cudaGetSymbolAddress((void**)&h_ptr, g_h);
        cudaDeviceGetAttribute(&n_sms, cudaDevAttrMultiProcessorCount, 0);
        cudaFuncSetAttribute(edge_kernel_ws,
                             cudaFuncAttributeMaxDynamicSharedMemorySize, SM_BYTES);
        cudaFuncSetAttribute(node_linear_mma,
                             cudaFuncAttributeMaxDynamicSharedMemorySize, NL_SMEM_BYTES);
    }

    cudaMemsetAsync(d_out, 0, (size_t)N_NODES * OUT_CH * sizeof(float), 0);
    node_linear_mma<<<(N_NODES + 127) / 128, 256, NL_SMEM_BYTES>>>(x, Wl, bl, h_ptr);
    edge_kernel_ws<<<n_sms, 512, SM_BYTES>>>(rbf, eidx, W1, b1, W2, b2,
                                             h_ptr, out, n_sms);
}